// round 1
// baseline (speedup 1.0000x reference)
#include <cuda_runtime.h>
#include <math.h>

#define T 2048        // B*S tokens
#define D 1024
#define Hh 2048
#define E 8
#define TWOH 4096
#define NSLOT (T * 2) // 4096 token-expert slots

// ---- scratch (static __device__ arrays; no allocation) ----
__device__ int   g_cnt[E];
__device__ int   g_list[E][T];          // slot ids grouped by expert
__device__ float g_wt[NSLOT];           // routing weight per slot
__device__ float g_hidden[(size_t)NSLOT * Hh]; // 32 MB
__device__ float g_yslot[(size_t)NSLOT * D];   // 16 MB
__device__ float g_aux;

__global__ void zero_kernel() {
    int i = threadIdx.x;
    if (i < E) g_cnt[i] = 0;
    if (i == 0) g_aux = 0.0f;
}

// One warp per token: logits over 8 experts, sigmoid, top-2, scatter.
__global__ void router_kernel(const float* __restrict__ x,
                              const float* __restrict__ rw,
                              const float* __restrict__ rb) {
    int warp = threadIdx.x >> 5;
    int lane = threadIdx.x & 31;
    int t = blockIdx.x * (blockDim.x >> 5) + warp;
    if (t >= T) return;

    const float* xr = x + (size_t)t * D;
    float acc[E];
#pragma unroll
    for (int e = 0; e < E; e++) acc[e] = 0.0f;

    for (int d = lane; d < D; d += 32) {
        float xv = xr[d];
#pragma unroll
        for (int e = 0; e < E; e++) acc[e] += xv * rw[e * D + d];
    }
#pragma unroll
    for (int e = 0; e < E; e++) {
#pragma unroll
        for (int off = 16; off; off >>= 1)
            acc[e] += __shfl_xor_sync(0xffffffffu, acc[e], off);
    }

    if (lane == 0) {
        float score[E];
        float auxl = 0.0f;
#pragma unroll
        for (int e = 0; e < E; e++) {
            float lg = acc[e] + rb[e];
            auxl += lg * lg;
            score[e] = 1.0f / (1.0f + expf(-lg));
        }
        // top-1 (first occurrence on ties, matching jax top_k)
        int e0 = 0;
#pragma unroll
        for (int e = 1; e < E; e++) if (score[e] > score[e0]) e0 = e;
        // top-2
        int e1 = -1;
#pragma unroll
        for (int e = 0; e < E; e++) {
            if (e == e0) continue;
            if (e1 < 0 || score[e] > score[e1]) e1 = e;
        }
        float s0 = score[e0], s1 = score[e1];
        float inv = 1.0f / (s0 + s1 + 1e-6f);
        g_wt[2 * t]     = s0 * inv;
        g_wt[2 * t + 1] = s1 * inv;
        int p0 = atomicAdd(&g_cnt[e0], 1); g_list[e0][p0] = 2 * t;
        int p1 = atomicAdd(&g_cnt[e1], 1); g_list[e1][p1] = 2 * t + 1;
        atomicAdd(&g_aux, auxl);
    }
}

__global__ void aux_kernel(float* __restrict__ out, int out_size) {
    if (out_size > T * D)
        out[T * D] = 0.01f * g_aux / (float)(T * E);
}

// GEMM1: hidden[slot, n] = silu(x@W1)[n] * (x@W2)[n], per-expert gathered rows.
// 64x64 tiles (two B tiles: W1 cols and W2 cols), BK=8, 256 thr, 4x4 micro.
__global__ void gemm1_kernel(const float* __restrict__ x,
                             const float* __restrict__ w12) {
    int e = blockIdx.z;
    int cnt = g_cnt[e];
    int m0 = blockIdx.y * 64;
    if (m0 >= cnt) return;
    int n0 = blockIdx.x * 64;

    __shared__ float As[8][64];
    __shared__ float Bs1[8][64];
    __shared__ float Bs2[8][64];
    __shared__ int   sslot[64];   // slot id for write (-1 => inactive row)
    __shared__ int   stok[64];    // token for x gather (always valid)

    int tid = threadIdx.x;
    if (tid < 64) {
        int m = m0 + tid;
        int s = g_list[e][(m < cnt) ? m : 0];
        sslot[tid] = (m < cnt) ? s : -1;
        stok[tid]  = s >> 1;
    }
    __syncthreads();

    float acc1[4][4] = {}, acc2[4][4] = {};
    int tx = tid & 15, ty = tid >> 4;
    const float* wbase = w12 + (size_t)e * D * TWOH;

    for (int k0 = 0; k0 < D; k0 += 8) {
        {   // A: 512 elems, 2 contiguous per thread
            int i = tid * 2;
            int m = i >> 3, kk = i & 7;
            const float* xp = x + (size_t)stok[m] * D + k0 + kk;
            As[kk][m]     = xp[0];
            As[kk + 1][m] = xp[1];
        }
        {   // B1/B2: 512 elems each
            int i = tid * 2;
            int kk = i >> 6, n = i & 63;
            const float* bp = wbase + (size_t)(k0 + kk) * TWOH + n0 + n;
            Bs1[kk][n]     = bp[0];
            Bs1[kk][n + 1] = bp[1];
            Bs2[kk][n]     = bp[Hh];
            Bs2[kk][n + 1] = bp[Hh + 1];
        }
        __syncthreads();
#pragma unroll
        for (int kk = 0; kk < 8; kk++) {
            float4 a  = *(const float4*)&As[kk][ty * 4];
            float4 b1 = *(const float4*)&Bs1[kk][tx * 4];
            float4 b2 = *(const float4*)&Bs2[kk][tx * 4];
            float av[4]  = {a.x, a.y, a.z, a.w};
            float b1v[4] = {b1.x, b1.y, b1.z, b1.w};
            float b2v[4] = {b2.x, b2.y, b2.z, b2.w};
#pragma unroll
            for (int r = 0; r < 4; r++)
#pragma unroll
                for (int c = 0; c < 4; c++) {
                    acc1[r][c] += av[r] * b1v[c];
                    acc2[r][c] += av[r] * b2v[c];
                }
        }
        __syncthreads();
    }

#pragma unroll
    for (int r = 0; r < 4; r++) {
        int s = sslot[ty * 4 + r];
        if (s < 0) continue;
        float4 o;
        float* ov = (float*)&o;
#pragma unroll
        for (int c = 0; c < 4; c++) {
            float h1 = acc1[r][c], h2 = acc2[r][c];
            float sil = h1 / (1.0f + expf(-h1));
            ov[c] = sil * h2;
        }
        *(float4*)(g_hidden + (size_t)s * Hh + n0 + tx * 4) = o;
    }
}

// GEMM2: yslot[slot, n] = wt[slot] * (hidden[slot,:] @ w3[e])[n]
__global__ void gemm2_kernel(const float* __restrict__ w3) {
    int e = blockIdx.z;
    int cnt = g_cnt[e];
    int m0 = blockIdx.y * 64;
    if (m0 >= cnt) return;
    int n0 = blockIdx.x * 64;

    __shared__ float As[8][64];
    __shared__ float Bs[8][64];
    __shared__ int   sslot[64];
    __shared__ int   ssrc[64];

    int tid = threadIdx.x;
    if (tid < 64) {
        int m = m0 + tid;
        int s = g_list[e][(m < cnt) ? m : 0];
        sslot[tid] = (m < cnt) ? s : -1;
        ssrc[tid]  = s;
    }
    __syncthreads();

    float acc[4][4] = {};
    int tx = tid & 15, ty = tid >> 4;
    const float* wbase = w3 + (size_t)e * Hh * D;

    for (int k0 = 0; k0 < Hh; k0 += 8) {
        {
            int i = tid * 2;
            int m = i >> 3, kk = i & 7;
            const float* ap = g_hidden + (size_t)ssrc[m] * Hh + k0 + kk;
            As[kk][m]     = ap[0];
            As[kk + 1][m] = ap[1];
        }
        {
            int i = tid * 2;
            int kk = i >> 6, n = i & 63;
            const float* bp = wbase + (size_t)(k0 + kk) * D + n0 + n;
            Bs[kk][n]     = bp[0];
            Bs[kk][n + 1] = bp[1];
        }
        __syncthreads();
#pragma unroll
        for (int kk = 0; kk < 8; kk++) {
            float4 a = *(const float4*)&As[kk][ty * 4];
            float4 b = *(const float4*)&Bs[kk][tx * 4];
            float av[4] = {a.x, a.y, a.z, a.w};
            float bv[4] = {b.x, b.y, b.z, b.w};
#pragma unroll
            for (int r = 0; r < 4; r++)
#pragma unroll
                for (int c = 0; c < 4; c++)
                    acc[r][c] += av[r] * bv[c];
        }
        __syncthreads();
    }

#pragma unroll
    for (int r = 0; r < 4; r++) {
        int s = sslot[ty * 4 + r];
        if (s < 0) continue;
        float w = g_wt[s];
        float4 o;
        float* ov = (float*)&o;
#pragma unroll
        for (int c = 0; c < 4; c++) ov[c] = w * acc[r][c];
        *(float4*)(g_yslot + (size_t)s * D + n0 + tx * 4) = o;
    }
}

// out[t, :] = yslot[2t, :] + yslot[2t+1, :]
__global__ void combine_kernel(float* __restrict__ out) {
    int i = blockIdx.x * blockDim.x + threadIdx.x; // float4 index
    const int total = T * D / 4;
    if (i >= total) return;
    int t = i / (D / 4);
    int j = i % (D / 4);
    float4 a = ((const float4*)(g_yslot + (size_t)(2 * t) * D))[j];
    float4 b = ((const float4*)(g_yslot + (size_t)(2 * t + 1) * D))[j];
    float4 o = {a.x + b.x, a.y + b.y, a.z + b.z, a.w + b.w};
    ((float4*)out)[i] = o;
}

extern "C" void kernel_launch(void* const* d_in, const int* in_sizes, int n_in,
                              void* d_out, int out_size) {
    const float* x   = (const float*)d_in[0];
    const float* rw  = (const float*)d_in[1];
    const float* rb  = (const float*)d_in[2];
    const float* w12 = (const float*)d_in[3];
    const float* w3  = (const float*)d_in[4];
    float* out = (float*)d_out;

    zero_kernel<<<1, 32>>>();
    router_kernel<<<T / 8, 256>>>(x, rw, rb);
    aux_kernel<<<1, 1>>>(out, out_size);
    // GEMM1: grid (H/64 col tiles, 32 max M tiles, E experts)
    gemm1_kernel<<<dim3(Hh / 64, 32, E), 256>>>(x, w12);
    // GEMM2: grid (D/64, 32, E)
    gemm2_kernel<<<dim3(D / 64, 32, E), 256>>>(w3);
    combine_kernel<<<(T * D / 4 + 255) / 256, 256>>>(out);
}

// round 4
// speedup vs baseline: 2.7588x; 2.7588x over previous
#include <cuda_runtime.h>
#include <cstdint>
#include <math.h>

#define T 2048        // B*S tokens
#define D 1024
#define Hh 2048
#define E 8
#define TWOH 4096
#define NSLOT (T * 2)

// ---- scratch ----
__device__ int   g_cnt[E];
__device__ int   g_list[E][T];
__device__ float g_wt[NSLOT];
__device__ float g_xr[(size_t)T * D];          // tf32-rounded x (8 MB)
__device__ float g_hidden[(size_t)NSLOT * Hh]; // 32 MB (tf32-rounded)
__device__ float g_yslot[(size_t)NSLOT * D];   // 16 MB
__device__ float g_aux;

// ======================= helpers =======================
__device__ __forceinline__ uint32_t smem_u32(const void* p) {
    uint32_t a;
    asm("{ .reg .u64 t; cvta.to.shared.u64 t, %1; cvt.u32.u64 %0, t; }" : "=r"(a) : "l"(p));
    return a;
}
__device__ __forceinline__ uint32_t f2tf(float f) {
    uint32_t r;
    asm("cvt.rna.tf32.f32 %0, %1;" : "=r"(r) : "f"(f));
    return r;
}
#define CP_ASYNC16(dst, src) \
    asm volatile("cp.async.cg.shared.global [%0], [%1], 16;" :: "r"(dst), "l"(src))
#define CP_COMMIT() asm volatile("cp.async.commit_group;")
#define CP_WAIT0()  asm volatile("cp.async.wait_group 0;" ::: "memory")

__device__ __forceinline__ void mma8(float* c, const uint32_t* a, uint32_t b0, uint32_t b1) {
    asm volatile(
        "mma.sync.aligned.m16n8k8.row.col.f32.tf32.tf32.f32 "
        "{%0,%1,%2,%3},{%4,%5,%6,%7},{%8,%9},{%0,%1,%2,%3};"
        : "+f"(c[0]), "+f"(c[1]), "+f"(c[2]), "+f"(c[3])
        : "r"(a[0]), "r"(a[1]), "r"(a[2]), "r"(a[3]), "r"(b0), "r"(b1));
}

// ======================= small kernels =======================
__global__ void zero_kernel() {
    int i = threadIdx.x;
    if (i < E) g_cnt[i] = 0;
    if (i == 0) g_aux = 0.0f;
}

__global__ void prep_x(const float* __restrict__ x) {
    int i = blockIdx.x * blockDim.x + threadIdx.x;
    if (i < T * D / 4) {
        float4 v = ((const float4*)x)[i];
        v.x = __uint_as_float(f2tf(v.x));
        v.y = __uint_as_float(f2tf(v.y));
        v.z = __uint_as_float(f2tf(v.z));
        v.w = __uint_as_float(f2tf(v.w));
        ((float4*)g_xr)[i] = v;
    }
}

__global__ void router_kernel(const float* __restrict__ x,
                              const float* __restrict__ rw,
                              const float* __restrict__ rb) {
    int warp = threadIdx.x >> 5;
    int lane = threadIdx.x & 31;
    int t = blockIdx.x * (blockDim.x >> 5) + warp;
    if (t >= T) return;

    const float* xr = x + (size_t)t * D;
    float acc[E];
#pragma unroll
    for (int e = 0; e < E; e++) acc[e] = 0.0f;
    for (int d = lane; d < D; d += 32) {
        float xv = xr[d];
#pragma unroll
        for (int e = 0; e < E; e++) acc[e] += xv * rw[e * D + d];
    }
#pragma unroll
    for (int e = 0; e < E; e++) {
#pragma unroll
        for (int off = 16; off; off >>= 1)
            acc[e] += __shfl_xor_sync(0xffffffffu, acc[e], off);
    }
    if (lane == 0) {
        float score[E];
        float auxl = 0.0f;
#pragma unroll
        for (int e = 0; e < E; e++) {
            float lg = acc[e] + rb[e];
            auxl += lg * lg;
            score[e] = 1.0f / (1.0f + expf(-lg));
        }
        int e0 = 0;
#pragma unroll
        for (int e = 1; e < E; e++) if (score[e] > score[e0]) e0 = e;
        int e1 = -1;
#pragma unroll
        for (int e = 0; e < E; e++) {
            if (e == e0) continue;
            if (e1 < 0 || score[e] > score[e1]) e1 = e;
        }
        float s0 = score[e0], s1 = score[e1];
        float inv = 1.0f / (s0 + s1 + 1e-6f);
        g_wt[2 * t]     = s0 * inv;
        g_wt[2 * t + 1] = s1 * inv;
        int p0 = atomicAdd(&g_cnt[e0], 1); g_list[e0][p0] = 2 * t;
        int p1 = atomicAdd(&g_cnt[e1], 1); g_list[e1][p1] = 2 * t + 1;
        atomicAdd(&g_aux, auxl);
    }
}

__global__ void aux_kernel(float* __restrict__ out, int out_size) {
    if (out_size > T * D)
        out[T * D] = 0.01f * g_aux / (float)(T * E);
}

__global__ void combine_kernel(float* __restrict__ out) {
    int i = blockIdx.x * blockDim.x + threadIdx.x;
    const int total = T * D / 4;
    if (i >= total) return;
    int t = i / (D / 4);
    int j = i % (D / 4);
    float4 a = ((const float4*)(g_yslot + (size_t)(2 * t) * D))[j];
    float4 b = ((const float4*)(g_yslot + (size_t)(2 * t + 1) * D))[j];
    float4 o = {a.x + b.x, a.y + b.y, a.z + b.z, a.w + b.w};
    ((float4*)out)[i] = o;
}

// ======================= GEMM1 =======================
// CTA 128x64 dual (W1,W2 cols), warp 32x32 per output. BK=32, 32 chunks.
// smem: slot[128]@0, tok[128]@512, A(st)@1024+st*18432 ([m][k] stride 36),
//       B1(st)@37888+st*9216, B2(st)@56320+st*9216 ([k][n] stride 72)
#define G1_SMEM 74752

__global__ void __launch_bounds__(256, 2) gemm1_kernel(const float* __restrict__ w12) {
    int e = blockIdx.z;
    int cnt = g_cnt[e];
    int m0 = blockIdx.x * 128;
    if (m0 >= cnt) return;
    int n0 = blockIdx.y * 64;

    extern __shared__ char smem[];
    uint32_t sb = smem_u32(smem);
    int* slot = (int*)smem;
    int* tok  = (int*)(smem + 512);
    int tid = threadIdx.x, wid = tid >> 5, lane = tid & 31;
    int g = lane >> 2, tg = lane & 3;
    int wm = (wid & 3) * 32, wn = (wid >> 2) * 32;

    if (tid < 128) {
        int m = m0 + tid;
        int s = g_list[e][(m < cnt) ? m : 0];
        slot[tid] = (m < cnt) ? s : -1;
        tok[tid]  = s >> 1;
    }
    __syncthreads();

    const float* wb0 = w12 + (size_t)e * D * TWOH + n0;
    float4 rb1[2], rb2[2];

    // prologue: A(0) async, B(0) staged
#pragma unroll
    for (int j = 0; j < 4; j++) {
        int c = tid + j * 256;
        int m = c >> 3, kq = c & 7;
        const float* src = g_xr + (size_t)tok[m] * D + kq * 4;
        CP_ASYNC16(sb + 1024 + m * 144 + kq * 16, src);
    }
    CP_COMMIT();
#pragma unroll
    for (int j = 0; j < 2; j++) {
        int c = tid + j * 256;
        int k = c >> 4, n4 = c & 15;
        const float* p = wb0 + (size_t)k * TWOH + n4 * 4;
        rb1[j] = *(const float4*)p;
        rb2[j] = *(const float4*)(p + Hh);
    }
    CP_WAIT0();
    {
#pragma unroll
        for (int j = 0; j < 2; j++) {
            int c = tid + j * 256;
            int k = c >> 4, n4 = c & 15;
            uint4 v1 = {f2tf(rb1[j].x), f2tf(rb1[j].y), f2tf(rb1[j].z), f2tf(rb1[j].w)};
            uint4 v2 = {f2tf(rb2[j].x), f2tf(rb2[j].y), f2tf(rb2[j].z), f2tf(rb2[j].w)};
            *(uint4*)(smem + 37888 + (k * 72 + n4 * 4) * 4) = v1;
            *(uint4*)(smem + 56320 + (k * 72 + n4 * 4) * 4) = v2;
        }
    }
    __syncthreads();

    float acc1[2][4][4] = {}, acc2[2][4][4] = {};

    for (int i = 0; i < 32; i++) {
        int cur = i & 1, nxt = cur ^ 1;
        if (i + 1 < 32) {
#pragma unroll
            for (int j = 0; j < 4; j++) {
                int c = tid + j * 256;
                int m = c >> 3, kq = c & 7;
                const float* src = g_xr + (size_t)tok[m] * D + (i + 1) * 32 + kq * 4;
                CP_ASYNC16(sb + 1024 + nxt * 18432 + m * 144 + kq * 16, src);
            }
            CP_COMMIT();
            const float* wb = wb0 + (size_t)(i + 1) * 32 * TWOH;
#pragma unroll
            for (int j = 0; j < 2; j++) {
                int c = tid + j * 256;
                int k = c >> 4, n4 = c & 15;
                const float* p = wb + (size_t)k * TWOH + n4 * 4;
                rb1[j] = *(const float4*)p;
                rb2[j] = *(const float4*)(p + Hh);
            }
        }
        // compute on cur
        {
            const uint32_t* A  = (const uint32_t*)(smem + 1024  + cur * 18432);
            const uint32_t* B1 = (const uint32_t*)(smem + 37888 + cur * 9216);
            const uint32_t* B2 = (const uint32_t*)(smem + 56320 + cur * 9216);
#pragma unroll
            for (int ks = 0; ks < 4; ks++) {
                uint32_t a[2][4];
#pragma unroll
                for (int mt = 0; mt < 2; mt++) {
                    int r = wm + mt * 16 + g;
                    a[mt][0] = A[r * 36 + ks * 8 + tg];
                    a[mt][1] = A[(r + 8) * 36 + ks * 8 + tg];
                    a[mt][2] = A[r * 36 + ks * 8 + tg + 4];
                    a[mt][3] = A[(r + 8) * 36 + ks * 8 + tg + 4];
                }
#pragma unroll
                for (int nt = 0; nt < 4; nt++) {
                    int nc = wn + nt * 8 + g;
                    uint32_t b10 = B1[(ks * 8 + tg) * 72 + nc];
                    uint32_t b11 = B1[(ks * 8 + tg + 4) * 72 + nc];
                    uint32_t b20 = B2[(ks * 8 + tg) * 72 + nc];
                    uint32_t b21 = B2[(ks * 8 + tg + 4) * 72 + nc];
#pragma unroll
                    for (int mt = 0; mt < 2; mt++) {
                        mma8(acc1[mt][nt], a[mt], b10, b11);
                        mma8(acc2[mt][nt], a[mt], b20, b21);
                    }
                }
            }
        }
        __syncthreads();
        if (i + 1 < 32) {
#pragma unroll
            for (int j = 0; j < 2; j++) {
                int c = tid + j * 256;
                int k = c >> 4, n4 = c & 15;
                uint4 v1 = {f2tf(rb1[j].x), f2tf(rb1[j].y), f2tf(rb1[j].z), f2tf(rb1[j].w)};
                uint4 v2 = {f2tf(rb2[j].x), f2tf(rb2[j].y), f2tf(rb2[j].z), f2tf(rb2[j].w)};
                *(uint4*)(smem + 37888 + nxt * 9216 + (k * 72 + n4 * 4) * 4) = v1;
                *(uint4*)(smem + 56320 + nxt * 9216 + (k * 72 + n4 * 4) * 4) = v2;
            }
            CP_WAIT0();
            __syncthreads();
        }
    }

    // epilogue: swiglu fuse, rna-round, store
#pragma unroll
    for (int mt = 0; mt < 2; mt++) {
        int r0 = wm + mt * 16 + g;
        int s0 = slot[r0], s1 = slot[r0 + 8];
#pragma unroll
        for (int nt = 0; nt < 4; nt++) {
            int col = n0 + wn + nt * 8 + tg * 2;
            if (s0 >= 0) {
                float h1a = acc1[mt][nt][0], h2a = acc2[mt][nt][0];
                float h1b = acc1[mt][nt][1], h2b = acc2[mt][nt][1];
                float oa = h2a * h1a / (1.0f + expf(-h1a));
                float ob = h2b * h1b / (1.0f + expf(-h1b));
                float2 v = {__uint_as_float(f2tf(oa)), __uint_as_float(f2tf(ob))};
                *(float2*)(g_hidden + (size_t)s0 * Hh + col) = v;
            }
            if (s1 >= 0) {
                float h1a = acc1[mt][nt][2], h2a = acc2[mt][nt][2];
                float h1b = acc1[mt][nt][3], h2b = acc2[mt][nt][3];
                float oa = h2a * h1a / (1.0f + expf(-h1a));
                float ob = h2b * h1b / (1.0f + expf(-h1b));
                float2 v = {__uint_as_float(f2tf(oa)), __uint_as_float(f2tf(ob))};
                *(float2*)(g_hidden + (size_t)s1 * Hh + col) = v;
            }
        }
    }
}

// ======================= GEMM2 =======================
// CTA 128x128, warp 32x64. K=2048, 64 chunks.
// smem: slot@0, src@512, A(st)@1024+st*18432, B(st)@37888+st*17408 (stride 136)
#define G2_SMEM 72704

__global__ void __launch_bounds__(256, 2) gemm2_kernel(const float* __restrict__ w3) {
    int e = blockIdx.z;
    int cnt = g_cnt[e];
    int m0 = blockIdx.x * 128;
    if (m0 >= cnt) return;
    int n0 = blockIdx.y * 128;

    extern __shared__ char smem[];
    uint32_t sb = smem_u32(smem);
    int* slot = (int*)smem;
    int* srcs = (int*)(smem + 512);
    int tid = threadIdx.x, wid = tid >> 5, lane = tid & 31;
    int g = lane >> 2, tg = lane & 3;
    int wm = (wid & 3) * 32, wn = (wid >> 2) * 64;

    if (tid < 128) {
        int m = m0 + tid;
        int s = g_list[e][(m < cnt) ? m : 0];
        slot[tid] = (m < cnt) ? s : -1;
        srcs[tid] = s;
    }
    __syncthreads();

    const float* wb0 = w3 + (size_t)e * Hh * D + n0;
    float4 rb[4];

#pragma unroll
    for (int j = 0; j < 4; j++) {
        int c = tid + j * 256;
        int m = c >> 3, kq = c & 7;
        const float* src = g_hidden + (size_t)srcs[m] * Hh + kq * 4;
        CP_ASYNC16(sb + 1024 + m * 144 + kq * 16, src);
    }
    CP_COMMIT();
#pragma unroll
    for (int j = 0; j < 4; j++) {
        int c = tid + j * 256;
        int k = c >> 5, n4 = c & 31;
        rb[j] = *(const float4*)(wb0 + (size_t)k * D + n4 * 4);
    }
    CP_WAIT0();
#pragma unroll
    for (int j = 0; j < 4; j++) {
        int c = tid + j * 256;
        int k = c >> 5, n4 = c & 31;
        uint4 v = {f2tf(rb[j].x), f2tf(rb[j].y), f2tf(rb[j].z), f2tf(rb[j].w)};
        *(uint4*)(smem + 37888 + (k * 136 + n4 * 4) * 4) = v;
    }
    __syncthreads();

    float acc[2][8][4] = {};

    for (int i = 0; i < 64; i++) {
        int cur = i & 1, nxt = cur ^ 1;
        if (i + 1 < 64) {
#pragma unroll
            for (int j = 0; j < 4; j++) {
                int c = tid + j * 256;
                int m = c >> 3, kq = c & 7;
                const float* src = g_hidden + (size_t)srcs[m] * Hh + (i + 1) * 32 + kq * 4;
                CP_ASYNC16(sb + 1024 + nxt * 18432 + m * 144 + kq * 16, src);
            }
            CP_COMMIT();
            const float* wb = wb0 + (size_t)(i + 1) * 32 * D;
#pragma unroll
            for (int j = 0; j < 4; j++) {
                int c = tid + j * 256;
                int k = c >> 5, n4 = c & 31;
                rb[j] = *(const float4*)(wb + (size_t)k * D + n4 * 4);
            }
        }
        {
            const uint32_t* A = (const uint32_t*)(smem + 1024  + cur * 18432);
            const uint32_t* B = (const uint32_t*)(smem + 37888 + cur * 17408);
#pragma unroll
            for (int ks = 0; ks < 4; ks++) {
                uint32_t a[2][4];
#pragma unroll
                for (int mt = 0; mt < 2; mt++) {
                    int r = wm + mt * 16 + g;
                    a[mt][0] = A[r * 36 + ks * 8 + tg];
                    a[mt][1] = A[(r + 8) * 36 + ks * 8 + tg];
                    a[mt][2] = A[r * 36 + ks * 8 + tg + 4];
                    a[mt][3] = A[(r + 8) * 36 + ks * 8 + tg + 4];
                }
#pragma unroll
                for (int nt = 0; nt < 8; nt++) {
                    int nc = wn + nt * 8 + g;
                    uint32_t b0 = B[(ks * 8 + tg) * 136 + nc];
                    uint32_t b1 = B[(ks * 8 + tg + 4) * 136 + nc];
#pragma unroll
                    for (int mt = 0; mt < 2; mt++)
                        mma8(acc[mt][nt], a[mt], b0, b1);
                }
            }
        }
        __syncthreads();
        if (i + 1 < 64) {
#pragma unroll
            for (int j = 0; j < 4; j++) {
                int c = tid + j * 256;
                int k = c >> 5, n4 = c & 31;
                uint4 v = {f2tf(rb[j].x), f2tf(rb[j].y), f2tf(rb[j].z), f2tf(rb[j].w)};
                *(uint4*)(smem + 37888 + nxt * 17408 + (k * 136 + n4 * 4) * 4) = v;
            }
            CP_WAIT0();
            __syncthreads();
        }
    }

#pragma unroll
    for (int mt = 0; mt < 2; mt++) {
        int r0 = wm + mt * 16 + g;
        int s0 = slot[r0], s1 = slot[r0 + 8];
        float w0 = (s0 >= 0) ? g_wt[s0] : 0.0f;
        float w1 = (s1 >= 0) ? g_wt[s1] : 0.0f;
#pragma unroll
        for (int nt = 0; nt < 8; nt++) {
            int col = n0 + wn + nt * 8 + tg * 2;
            if (s0 >= 0) {
                float2 v = {w0 * acc[mt][nt][0], w0 * acc[mt][nt][1]};
                *(float2*)(g_yslot + (size_t)s0 * D + col) = v;
            }
            if (s1 >= 0) {
                float2 v = {w1 * acc[mt][nt][2], w1 * acc[mt][nt][3]};
                *(float2*)(g_yslot + (size_t)s1 * D + col) = v;
            }
        }
    }
}

// ======================= launch =======================
extern "C" void kernel_launch(void* const* d_in, const int* in_sizes, int n_in,
                              void* d_out, int out_size) {
    const float* x   = (const float*)d_in[0];
    const float* rw  = (const float*)d_in[1];
    const float* rb  = (const float*)d_in[2];
    const float* w12 = (const float*)d_in[3];
    const float* w3  = (const float*)d_in[4];
    float* out = (float*)d_out;

    cudaFuncSetAttribute(gemm1_kernel, cudaFuncAttributeMaxDynamicSharedMemorySize, G1_SMEM);
    cudaFuncSetAttribute(gemm2_kernel, cudaFuncAttributeMaxDynamicSharedMemorySize, G2_SMEM);

    zero_kernel<<<1, 32>>>();
    prep_x<<<(T * D / 4 + 255) / 256, 256>>>(x);
    router_kernel<<<T / 8, 256>>>(x, rw, rb);
    aux_kernel<<<1, 1>>>(out, out_size);
    gemm1_kernel<<<dim3(16, 32, E), 256, G1_SMEM>>>(w12);
    gemm2_kernel<<<dim3(16, 8, E), 256, G2_SMEM>>>(w3);
    combine_kernel<<<(T * D / 4 + 255) / 256, 256>>>(out);
}

// round 5
// speedup vs baseline: 6.8922x; 2.4983x over previous
#include <cuda_runtime.h>
#include <cuda_fp16.h>
#include <cstdint>
#include <math.h>

#define T 2048        // B*S tokens
#define D 1024
#define Hh 2048
#define E 8
#define TWOH 4096
#define NSLOT (T * 2)

// ---- scratch ----
__device__ int    g_cnt[E];
__device__ int    g_list[E][T];
__device__ float  g_wt[NSLOT];
__device__ __half g_xh[(size_t)T * D];            // fp16 x (4 MB)
__device__ __half g_hiddenh[(size_t)NSLOT * Hh];  // fp16 hidden (16 MB)
__device__ float  g_yslot[(size_t)NSLOT * D];     // 16 MB
__device__ float  g_aux;

// ======================= helpers =======================
__device__ __forceinline__ uint32_t smem_u32(const void* p) {
    uint32_t a;
    asm("{ .reg .u64 t; cvta.to.shared.u64 t, %1; cvt.u32.u64 %0, t; }" : "=r"(a) : "l"(p));
    return a;
}
__device__ __forceinline__ uint32_t h2u(__half2 h) { return *(uint32_t*)&h; }

#define CP_ASYNC16(dst, src) \
    asm volatile("cp.async.cg.shared.global [%0], [%1], 16;" :: "r"(dst), "l"(src))
#define CP_COMMIT() asm volatile("cp.async.commit_group;")
#define CP_WAIT0()  asm volatile("cp.async.wait_group 0;" ::: "memory")

__device__ __forceinline__ void ldsm4(uint32_t* r, uint32_t addr) {
    asm volatile("ldmatrix.sync.aligned.m8n8.x4.shared.b16 {%0,%1,%2,%3},[%4];"
        : "=r"(r[0]), "=r"(r[1]), "=r"(r[2]), "=r"(r[3]) : "r"(addr));
}
__device__ __forceinline__ void ldsm4t(uint32_t* r, uint32_t addr) {
    asm volatile("ldmatrix.sync.aligned.m8n8.x4.trans.shared.b16 {%0,%1,%2,%3},[%4];"
        : "=r"(r[0]), "=r"(r[1]), "=r"(r[2]), "=r"(r[3]) : "r"(addr));
}
__device__ __forceinline__ void mma16(float* c, const uint32_t* a, uint32_t b0, uint32_t b1) {
    asm volatile(
        "mma.sync.aligned.m16n8k16.row.col.f32.f16.f16.f32 "
        "{%0,%1,%2,%3},{%4,%5,%6,%7},{%8,%9},{%0,%1,%2,%3};"
        : "+f"(c[0]), "+f"(c[1]), "+f"(c[2]), "+f"(c[3])
        : "r"(a[0]), "r"(a[1]), "r"(a[2]), "r"(a[3]), "r"(b0), "r"(b1));
}

// ======================= small kernels =======================
__global__ void zero_kernel() {
    int i = threadIdx.x;
    if (i < E) g_cnt[i] = 0;
    if (i == 0) g_aux = 0.0f;
}

__global__ void prep_x(const float* __restrict__ x) {
    int i = blockIdx.x * blockDim.x + threadIdx.x;
    if (i < T * D / 4) {
        float4 v = ((const float4*)x)[i];
        uint2 u;
        u.x = h2u(__floats2half2_rn(v.x, v.y));
        u.y = h2u(__floats2half2_rn(v.z, v.w));
        ((uint2*)g_xh)[i] = u;
    }
}

__global__ void router_kernel(const float* __restrict__ x,
                              const float* __restrict__ rw,
                              const float* __restrict__ rb) {
    int warp = threadIdx.x >> 5;
    int lane = threadIdx.x & 31;
    int t = blockIdx.x * (blockDim.x >> 5) + warp;
    if (t >= T) return;

    const float* xr = x + (size_t)t * D;
    float acc[E];
#pragma unroll
    for (int e = 0; e < E; e++) acc[e] = 0.0f;
    for (int d = lane; d < D; d += 32) {
        float xv = xr[d];
#pragma unroll
        for (int e = 0; e < E; e++) acc[e] += xv * rw[e * D + d];
    }
#pragma unroll
    for (int e = 0; e < E; e++) {
#pragma unroll
        for (int off = 16; off; off >>= 1)
            acc[e] += __shfl_xor_sync(0xffffffffu, acc[e], off);
    }
    if (lane == 0) {
        float score[E];
        float auxl = 0.0f;
#pragma unroll
        for (int e = 0; e < E; e++) {
            float lg = acc[e] + rb[e];
            auxl += lg * lg;
            score[e] = 1.0f / (1.0f + expf(-lg));
        }
        int e0 = 0;
#pragma unroll
        for (int e = 1; e < E; e++) if (score[e] > score[e0]) e0 = e;
        int e1 = -1;
#pragma unroll
        for (int e = 0; e < E; e++) {
            if (e == e0) continue;
            if (e1 < 0 || score[e] > score[e1]) e1 = e;
        }
        float s0 = score[e0], s1 = score[e1];
        float inv = 1.0f / (s0 + s1 + 1e-6f);
        g_wt[2 * t]     = s0 * inv;
        g_wt[2 * t + 1] = s1 * inv;
        int p0 = atomicAdd(&g_cnt[e0], 1); g_list[e0][p0] = 2 * t;
        int p1 = atomicAdd(&g_cnt[e1], 1); g_list[e1][p1] = 2 * t + 1;
        atomicAdd(&g_aux, auxl);
    }
}

__global__ void aux_kernel(float* __restrict__ out, int out_size) {
    if (out_size > T * D)
        out[T * D] = 0.01f * g_aux / (float)(T * E);
}

__global__ void combine_kernel(float* __restrict__ out) {
    int i = blockIdx.x * blockDim.x + threadIdx.x;
    const int total = T * D / 4;
    if (i >= total) return;
    int t = i / (D / 4);
    int j = i % (D / 4);
    float4 a = ((const float4*)(g_yslot + (size_t)(2 * t) * D))[j];
    float4 b = ((const float4*)(g_yslot + (size_t)(2 * t + 1) * D))[j];
    float4 o = {a.x + b.x, a.y + b.y, a.z + b.z, a.w + b.w};
    ((float4*)out)[i] = o;
}

// ======================= GEMM common layout =======================
// A: [m:128][k:64] fp16, row stride 144B (64 halfs + 8 pad). stage = 18432B
// B: [k:64][n:128] fp16, row stride 272B (128 halfs + 8 pad). stage = 17408B
#define A_OFF 1024
#define A_STG 18432
#define B_OFF (1024 + 2 * 18432)
#define B_STG 17408
#define G_SMEM (B_OFF + 2 * 17408)

// ======================= GEMM1 =======================
// hidden[slot, n] = silu(xh@W1)[n] * (xh@W2)[n]. CTA 128m x 64n dual. KC=64, 16 chunks.
__global__ void __launch_bounds__(256, 2) gemm1_kernel(const float* __restrict__ w12) {
    int e = blockIdx.z;
    int cnt = g_cnt[e];
    int m0 = blockIdx.x * 128;
    if (m0 >= cnt) return;
    int n0 = blockIdx.y * 64;

    extern __shared__ char smem[];
    uint32_t sb = smem_u32(smem);
    int* slot = (int*)smem;
    int* tok  = (int*)(smem + 512);
    int tid = threadIdx.x, wid = tid >> 5, lane = tid & 31;
    int g = lane >> 2, tg = lane & 3;
    int wm = (wid & 3) * 32, wn = (wid >> 2) * 32;
    int q = lane >> 3, r = lane & 7;

    if (tid < 128) {
        int m = m0 + tid;
        int s = g_list[e][(m < cnt) ? m : 0];
        slot[tid] = (m < cnt) ? s : -1;
        tok[tid]  = s >> 1;
    }
    __syncthreads();

    const float* wb0 = w12 + (size_t)e * D * TWOH;
    // per-thread cp.async A params
    int am = tid >> 1;                       // unused pattern below uses c loop
    (void)am;
    // per-lane ldmatrix bases
    uint32_t aBase = sb + A_OFF + (uint32_t)((wm + (q & 1) * 8 + r) * 144 + (q >> 1) * 16);
    uint32_t bBase = sb + B_OFF + (uint32_t)(((q & 1) * 8 + r) * 272 + (q >> 1) * 16);

    float4 rbv[8];

    // ---- prologue: A(0) cp.async, B(0) reg-stage ----
#pragma unroll
    for (int j = 0; j < 4; j++) {
        int c = tid + j * 256;
        int m = c >> 3, kq = c & 7;
        const __half* src = g_xh + (size_t)tok[m] * D + kq * 8;
        CP_ASYNC16(sb + A_OFF + m * 144 + kq * 16, src);
    }
    CP_COMMIT();
#pragma unroll
    for (int j = 0; j < 8; j++) {
        int c = tid + j * 256;
        int k = c >> 5, n4 = c & 31;
        int col = (n4 < 16) ? (n0 + n4 * 4) : (Hh + n0 + (n4 - 16) * 4);
        rbv[j] = *(const float4*)(wb0 + (size_t)k * TWOH + col);
    }
#pragma unroll
    for (int j = 0; j < 8; j++) {
        int c = tid + j * 256;
        int k = c >> 5, n4 = c & 31;
        uint2 u;
        u.x = h2u(__floats2half2_rn(rbv[j].x, rbv[j].y));
        u.y = h2u(__floats2half2_rn(rbv[j].z, rbv[j].w));
        *(uint2*)(smem + B_OFF + k * 272 + n4 * 8) = u;
    }
    CP_WAIT0();
    __syncthreads();

    float acc1[2][4][4] = {}, acc2[2][4][4] = {};

    for (int i = 0; i < 16; i++) {
        int cur = i & 1, nxt = cur ^ 1;
        if (i + 1 < 16) {
            int k0 = (i + 1) * 64;
#pragma unroll
            for (int j = 0; j < 4; j++) {
                int c = tid + j * 256;
                int m = c >> 3, kq = c & 7;
                const __half* src = g_xh + (size_t)tok[m] * D + k0 + kq * 8;
                CP_ASYNC16(sb + A_OFF + nxt * A_STG + m * 144 + kq * 16, src);
            }
            CP_COMMIT();
#pragma unroll
            for (int j = 0; j < 8; j++) {
                int c = tid + j * 256;
                int k = c >> 5, n4 = c & 31;
                int col = (n4 < 16) ? (n0 + n4 * 4) : (Hh + n0 + (n4 - 16) * 4);
                rbv[j] = *(const float4*)(wb0 + (size_t)(k0 + k) * TWOH + col);
            }
        }
        // compute on cur
        {
            uint32_t aA = aBase + cur * A_STG;
            uint32_t bA = bBase + cur * B_STG;
#pragma unroll
            for (int kt = 0; kt < 4; kt++) {
                uint32_t a[2][4];
                ldsm4(a[0], aA + kt * 32);
                ldsm4(a[1], aA + kt * 32 + 16 * 144);
                uint32_t b1[8], b2[8];
                uint32_t bk = bA + kt * (16 * 272);
                ldsm4t(b1 + 0, bk + (wn + 0) * 2);
                ldsm4t(b1 + 4, bk + (wn + 16) * 2);
                ldsm4t(b2 + 0, bk + (64 + wn) * 2);
                ldsm4t(b2 + 4, bk + (64 + wn + 16) * 2);
#pragma unroll
                for (int nt = 0; nt < 4; nt++) {
#pragma unroll
                    for (int mt = 0; mt < 2; mt++) {
                        mma16(acc1[mt][nt], a[mt], b1[2 * nt], b1[2 * nt + 1]);
                        mma16(acc2[mt][nt], a[mt], b2[2 * nt], b2[2 * nt + 1]);
                    }
                }
            }
        }
        if (i + 1 < 16) {
#pragma unroll
            for (int j = 0; j < 8; j++) {
                int c = tid + j * 256;
                int k = c >> 5, n4 = c & 31;
                uint2 u;
                u.x = h2u(__floats2half2_rn(rbv[j].x, rbv[j].y));
                u.y = h2u(__floats2half2_rn(rbv[j].z, rbv[j].w));
                *(uint2*)(smem + B_OFF + nxt * B_STG + k * 272 + n4 * 8) = u;
            }
        }
        CP_WAIT0();
        __syncthreads();
    }

    // epilogue: swiglu fuse, store fp16 hidden
#pragma unroll
    for (int mt = 0; mt < 2; mt++) {
        int r0 = wm + mt * 16 + g;
        int s0 = slot[r0], s1 = slot[r0 + 8];
#pragma unroll
        for (int nt = 0; nt < 4; nt++) {
            int col = n0 + wn + nt * 8 + tg * 2;
            if (s0 >= 0) {
                float h1a = acc1[mt][nt][0], h2a = acc2[mt][nt][0];
                float h1b = acc1[mt][nt][1], h2b = acc2[mt][nt][1];
                float oa = h2a * h1a / (1.0f + expf(-h1a));
                float ob = h2b * h1b / (1.0f + expf(-h1b));
                *(uint32_t*)(g_hiddenh + (size_t)s0 * Hh + col) = h2u(__floats2half2_rn(oa, ob));
            }
            if (s1 >= 0) {
                float h1a = acc1[mt][nt][2], h2a = acc2[mt][nt][2];
                float h1b = acc1[mt][nt][3], h2b = acc2[mt][nt][3];
                float oa = h2a * h1a / (1.0f + expf(-h1a));
                float ob = h2b * h1b / (1.0f + expf(-h1b));
                *(uint32_t*)(g_hiddenh + (size_t)s1 * Hh + col) = h2u(__floats2half2_rn(oa, ob));
            }
        }
    }
}

// ======================= GEMM2 =======================
// yslot[slot, n] = wt[slot] * (hiddenh @ w3)[n]. CTA 128m x 128n. KC=64, 32 chunks.
__global__ void __launch_bounds__(256, 2) gemm2_kernel(const float* __restrict__ w3) {
    int e = blockIdx.z;
    int cnt = g_cnt[e];
    int m0 = blockIdx.x * 128;
    if (m0 >= cnt) return;
    int n0 = blockIdx.y * 128;

    extern __shared__ char smem[];
    uint32_t sb = smem_u32(smem);
    int* slot = (int*)smem;
    int* srcs = (int*)(smem + 512);
    int tid = threadIdx.x, wid = tid >> 5, lane = tid & 31;
    int g = lane >> 2, tg = lane & 3;
    int wm = (wid & 3) * 32, wn = (wid >> 2) * 64;
    int q = lane >> 3, r = lane & 7;

    if (tid < 128) {
        int m = m0 + tid;
        int s = g_list[e][(m < cnt) ? m : 0];
        slot[tid] = (m < cnt) ? s : -1;
        srcs[tid] = s;
    }
    __syncthreads();

    const float* wb0 = w3 + (size_t)e * Hh * D + n0;
    uint32_t aBase = sb + A_OFF + (uint32_t)((wm + (q & 1) * 8 + r) * 144 + (q >> 1) * 16);
    uint32_t bBase = sb + B_OFF + (uint32_t)(((q & 1) * 8 + r) * 272 + (q >> 1) * 16);

    float4 rbv[8];

#pragma unroll
    for (int j = 0; j < 4; j++) {
        int c = tid + j * 256;
        int m = c >> 3, kq = c & 7;
        const __half* src = g_hiddenh + (size_t)srcs[m] * Hh + kq * 8;
        CP_ASYNC16(sb + A_OFF + m * 144 + kq * 16, src);
    }
    CP_COMMIT();
#pragma unroll
    for (int j = 0; j < 8; j++) {
        int c = tid + j * 256;
        int k = c >> 5, n4 = c & 31;
        rbv[j] = *(const float4*)(wb0 + (size_t)k * D + n4 * 4);
    }
#pragma unroll
    for (int j = 0; j < 8; j++) {
        int c = tid + j * 256;
        int k = c >> 5, n4 = c & 31;
        uint2 u;
        u.x = h2u(__floats2half2_rn(rbv[j].x, rbv[j].y));
        u.y = h2u(__floats2half2_rn(rbv[j].z, rbv[j].w));
        *(uint2*)(smem + B_OFF + k * 272 + n4 * 8) = u;
    }
    CP_WAIT0();
    __syncthreads();

    float acc[2][8][4] = {};

    for (int i = 0; i < 32; i++) {
        int cur = i & 1, nxt = cur ^ 1;
        if (i + 1 < 32) {
            int k0 = (i + 1) * 64;
#pragma unroll
            for (int j = 0; j < 4; j++) {
                int c = tid + j * 256;
                int m = c >> 3, kq = c & 7;
                const __half* src = g_hiddenh + (size_t)srcs[m] * Hh + k0 + kq * 8;
                CP_ASYNC16(sb + A_OFF + nxt * A_STG + m * 144 + kq * 16, src);
            }
            CP_COMMIT();
#pragma unroll
            for (int j = 0; j < 8; j++) {
                int c = tid + j * 256;
                int k = c >> 5, n4 = c & 31;
                rbv[j] = *(const float4*)(wb0 + (size_t)(k0 + k) * D + n4 * 4);
            }
        }
        {
            uint32_t aA = aBase + cur * A_STG;
            uint32_t bA = bBase + cur * B_STG;
#pragma unroll
            for (int kt = 0; kt < 4; kt++) {
                uint32_t a[2][4];
                ldsm4(a[0], aA + kt * 32);
                ldsm4(a[1], aA + kt * 32 + 16 * 144);
                uint32_t b[16];
                uint32_t bk = bA + kt * (16 * 272);
                ldsm4t(b + 0,  bk + (wn + 0) * 2);
                ldsm4t(b + 4,  bk + (wn + 16) * 2);
                ldsm4t(b + 8,  bk + (wn + 32) * 2);
                ldsm4t(b + 12, bk + (wn + 48) * 2);
#pragma unroll
                for (int nt = 0; nt < 8; nt++) {
#pragma unroll
                    for (int mt = 0; mt < 2; mt++)
                        mma16(acc[mt][nt], a[mt], b[2 * nt], b[2 * nt + 1]);
                }
            }
        }
        if (i + 1 < 32) {
#pragma unroll
            for (int j = 0; j < 8; j++) {
                int c = tid + j * 256;
                int k = c >> 5, n4 = c & 31;
                uint2 u;
                u.x = h2u(__floats2half2_rn(rbv[j].x, rbv[j].y));
                u.y = h2u(__floats2half2_rn(rbv[j].z, rbv[j].w));
                *(uint2*)(smem + B_OFF + nxt * B_STG + k * 272 + n4 * 8) = u;
            }
        }
        CP_WAIT0();
        __syncthreads();
    }

#pragma unroll
    for (int mt = 0; mt < 2; mt++) {
        int r0 = wm + mt * 16 + g;
        int s0 = slot[r0], s1 = slot[r0 + 8];
        float w0 = (s0 >= 0) ? g_wt[s0] : 0.0f;
        float w1 = (s1 >= 0) ? g_wt[s1] : 0.0f;
#pragma unroll
        for (int nt = 0; nt < 8; nt++) {
            int col = n0 + wn + nt * 8 + tg * 2;
            if (s0 >= 0) {
                float2 v = {w0 * acc[mt][nt][0], w0 * acc[mt][nt][1]};
                *(float2*)(g_yslot + (size_t)s0 * D + col) = v;
            }
            if (s1 >= 0) {
                float2 v = {w1 * acc[mt][nt][2], w1 * acc[mt][nt][3]};
                *(float2*)(g_yslot + (size_t)s1 * D + col) = v;
            }
        }
    }
}

// ======================= launch =======================
extern "C" void kernel_launch(void* const* d_in, const int* in_sizes, int n_in,
                              void* d_out, int out_size) {
    const float* x   = (const float*)d_in[0];
    const float* rw  = (const float*)d_in[1];
    const float* rb  = (const float*)d_in[2];
    const float* w12 = (const float*)d_in[3];
    const float* w3  = (const float*)d_in[4];
    float* out = (float*)d_out;

    cudaFuncSetAttribute(gemm1_kernel, cudaFuncAttributeMaxDynamicSharedMemorySize, G_SMEM);
    cudaFuncSetAttribute(gemm2_kernel, cudaFuncAttributeMaxDynamicSharedMemorySize, G_SMEM);

    zero_kernel<<<1, 32>>>();
    prep_x<<<(T * D / 4 + 255) / 256, 256>>>(x);
    router_kernel<<<T / 8, 256>>>(x, rw, rb);
    aux_kernel<<<1, 1>>>(out, out_size);
    gemm1_kernel<<<dim3(16, 32, E), 256, G_SMEM>>>(w12);
    gemm2_kernel<<<dim3(16, 8, E), 256, G_SMEM>>>(w3);
    combine_kernel<<<(T * D / 4 + 255) / 256, 256>>>(out);
}